// round 14
// baseline (speedup 1.0000x reference)
#include <cuda_runtime.h>
#include <cuda_fp16.h>
#include <cstdint>

#define S_DIM 512
#define O_DIM 4096
#define I_DIM 4096

// ===================== device-global scratch ===============================
__device__ float g_P1[O_DIM], g_N1[O_DIM], g_P2[O_DIM], g_PB[O_DIM], g_NB[O_DIM];
__device__ float g_nrb[O_DIM];
__device__ float g_D[S_DIM];
__device__ int   g_anyC2 = 0;   // static init; atomicOr idempotent across replays

// fp16 coefficient matrices (A side). W converts to fp16 inside the GEMM.
__device__ __align__(16) __half g_A1 [S_DIM * O_DIM];
__device__ __align__(16) __half g_A2 [S_DIM * O_DIM];

__device__ __forceinline__ uint32_t smem_u32(const void* p) {
    uint32_t a;
    asm("{ .reg .u64 t; cvta.to.shared.u64 t, %1; cvt.u32.u64 %0, t; }"
        : "=r"(a) : "l"(p));
    return a;
}
#define CP_ASYNC16(s, g) \
    asm volatile("cp.async.cg.shared.global [%0], [%1], 16;" :: "r"(s), "l"(g))
#define CP_COMMIT() asm volatile("cp.async.commit_group;" ::: "memory")
#define CP_WAIT1()  asm volatile("cp.async.wait_group 1;" ::: "memory")
#define CP_WAIT2()  asm volatile("cp.async.wait_group 2;" ::: "memory")

__device__ __forceinline__ void ldmx4(uint32_t* r, uint32_t addr) {
    asm volatile("ldmatrix.sync.aligned.m8n8.x4.shared.b16 {%0,%1,%2,%3}, [%4];"
                 : "=r"(r[0]), "=r"(r[1]), "=r"(r[2]), "=r"(r[3]) : "r"(addr));
}
__device__ __forceinline__ void ldmx2t(uint32_t* r, uint32_t addr) {
    asm volatile("ldmatrix.sync.aligned.m8n8.x2.trans.shared.b16 {%0,%1}, [%2];"
                 : "=r"(r[0]), "=r"(r[1]) : "r"(addr));
}
__device__ __forceinline__ void mma_f16(float* c, const uint32_t* a, const uint32_t* b) {
    asm volatile("mma.sync.aligned.m16n8k16.row.col.f32.f16.f16.f32 "
                 "{%0,%1,%2,%3}, {%4,%5,%6,%7}, {%8,%9}, {%0,%1,%2,%3};"
                 : "+f"(c[0]), "+f"(c[1]), "+f"(c[2]), "+f"(c[3])
                 : "r"(a[0]), "r"(a[1]), "r"(a[2]), "r"(a[3]), "r"(b[0]), "r"(b[1]));
}

// ===================== kernel 1: per-neuron scalars ========================
__global__ void kern_prep(const float* __restrict__ bias,
                          const float* __restrict__ lbp,
                          const float* __restrict__ ubp,
                          const float* __restrict__ alpha) {
    int o = blockIdx.x * blockDim.x + threadIdx.x;
    if (o >= O_DIM) return;
    float b  = bias[o];
    float lb = lbp[o];
    float ub = ubp[o];
    float a  = alpha[o];
    float one_a = 1.0f - a;

    float lb_r = fminf(lb, 0.0f);
    float ub_r = fmaxf(ub, 0.0f);
    ub_r = fmaxf(ub_r, lb_r + 1e-8f);
    float ud  = ub_r / (ub_r - lb_r);
    float upb = -lb_r * ud;
    float ld  = (ud > 0.5f) ? 1.0f : 0.0f;
    float lower_d = (fabsf(lb) >= fabsf(ub)) ? 1.0f : 0.0f;

    float P1, N1, P2, PB, NB;
    if (ub <= 0.0f) {
        P1 = a * ud;            N1 = a * ld;                     P2 = 0.0f;
        PB = upb + ud * a * b;  NB = ld * a * b;
    } else if (lb >= 0.0f) {
        P1 = a * ud + one_a;    N1 = a * ld + one_a;             P2 = 0.0f;
        PB = one_a * b + upb + ud * a * b;
        NB = one_a * b + ld * a * b;
    } else {
        P1 = a * ud;            N1 = a * ld + one_a * lower_d;   P2 = one_a;
        PB = one_a * fmaxf(b, 0.0f) + upb + ud * a * b;
        NB = one_a * lower_d * b + ld * a * b;
    }
    g_P1[o] = P1; g_N1[o] = N1; g_P2[o] = P2;
    g_PB[o] = PB; g_NB[o] = NB;
    g_nrb[o] = -fmaxf(b, 0.0f);
    if (P2 != 0.0f) atomicOr(&g_anyC2, 1);
}

// ===================== kernel 2: coefficients (fp16) + ubias + D ===========
__global__ void kern_coeff(const float* __restrict__ last_uA,
                           float* __restrict__ ubias_out) {
    int s = blockIdx.x;
    const bool useC2 = (g_anyC2 != 0);
    const float* row = last_uA + (size_t)s * O_DIM;

    float accB = 0.0f, accD = 0.0f;
    for (int o = threadIdx.x; o < O_DIM; o += blockDim.x) {
        float u = row[o];
        float p = fmaxf(u, 0.0f);
        float n = fminf(u, 0.0f);
        float c1 = p * g_P1[o] + n * g_N1[o];
        float c2 = p * g_P2[o];
        size_t idx = (size_t)s * O_DIM + o;
        g_A1[idx] = __float2half_rn(c1);
        if (useC2) g_A2[idx] = __float2half_rn(c2);
        accB = fmaf(p, g_PB[o], accB);
        accB = fmaf(n, g_NB[o], accB);
        accD = fmaf(c2, g_nrb[o], accD);
    }
    __shared__ float sB[8], sD[8];
    #pragma unroll
    for (int off = 16; off > 0; off >>= 1) {
        accB += __shfl_down_sync(0xffffffffu, accB, off);
        accD += __shfl_down_sync(0xffffffffu, accD, off);
    }
    int wid = threadIdx.x >> 5, lid = threadIdx.x & 31;
    if (lid == 0) { sB[wid] = accB; sD[wid] = accD; }
    __syncthreads();
    if (threadIdx.x == 0) {
        float tB = 0.0f, tD = 0.0f;
        #pragma unroll
        for (int w = 0; w < 8; w++) { tB += sB[w]; tD += sD[w]; }
        ubias_out[s] = tB;
        g_D[s] = tD;
    }
}

// ===================== kernel 3: GEMM + fused W->fp16 conversion ===========
// out[m,i] = sum_o fp16(C1)[m,o]*fp16(W)[o,i] (+ C2*relu(W+b) path) + D[m]
// 512 threads, 16 warps (4/SMSP). Rings: A fp16 x4, W fp32 x3, B fp16 x2.
// Race-free: wait_group 1 -> barrier -> load(kt+3) -> convert(kt+1) -> compute(kt).
#define BM 128
#define BN 128
#define BK 64
#define NTHR 512
#define LDA 72                       // fp16 elems per A row (144 B)
#define LDB 136                      // fp16 elems per B16 row (272 B)
#define A_BYTES   (BM * LDA * 2)     // 18432
#define B32_BYTES (BK * BN * 4)      // 32768
#define B16_BYTES (BK * LDB * 2)     // 17408
#define A_OFF    0
#define B32_OFF  (4 * A_BYTES)                  // 73728
#define B16_OFF  (B32_OFF + 3 * B32_BYTES)      // 172032
#define SMEM_DYN (B16_OFF + 2 * B16_BYTES)      // 206848

__global__ void __launch_bounds__(NTHR, 1)
kern_gemm_mma(const float* __restrict__ W,
              const float* __restrict__ bias,
              float* __restrict__ out) {
    extern __shared__ char sm[];
    const uint32_t sbase = smem_u32(sm);

    const int tid  = threadIdx.x;
    const int wid  = tid >> 5;
    const int lane = tid & 31;
    const int bn = blockIdx.x * BN;
    const int bm = blockIdx.y * BM;
    const bool useC2 = (g_anyC2 != 0);
    const int nK = useC2 ? 128 : 64;

    const int warp_m = wid & 3;      // 0..3 -> 32 rows each
    const int warp_n = wid >> 2;     // 0..3 -> 32 cols each

    float acc[2][4][4];
    #pragma unroll
    for (int mi = 0; mi < 2; mi++)
        #pragma unroll
        for (int ni = 0; ni < 4; ni++)
            #pragma unroll
            for (int q = 0; q < 4; q++) acc[mi][ni][q] = 0.0f;

    // ---- stage load: A fp16 (1024 chunks) + W fp32 (2048 chunks) ----------
    auto load_stage = [&](int ktL) {
        const int k0 = (ktL & 63) * BK;
        const __half* pA = (ktL < 64) ? g_A1 : g_A2;
        const uint32_t sA   = sbase + A_OFF + (ktL & 3) * A_BYTES;
        const uint32_t sB32 = sbase + B32_OFF + (ktL % 3) * B32_BYTES;

        #pragma unroll
        for (int j = 0; j < 2; j++) {           // A: 128 rows x 8 chunks
            int id = tid + NTHR * j;
            int ar = id >> 3, ac = id & 7;
            size_t gA = (size_t)(bm + ar) * O_DIM + k0 + ac * 8;
            CP_ASYNC16(sA + ar * (LDA * 2) + ac * 16, pA + gA);
        }
        #pragma unroll
        for (int j = 0; j < 4; j++) {           // W fp32: 64 rows x 32 chunks
            int id = tid + NTHR * j;
            int br = id >> 5, bc = id & 31;
            size_t gB = (size_t)(k0 + br) * I_DIM + bn + bc * 4;
            CP_ASYNC16(sB32 + br * 512 + bc * 16, W + gB);
        }
    };

    // ---- convert stage ktc: fp32 staging -> fp16 B tile (relu+b if C2) ----
    auto convert_stage = [&](int ktc) {
        const uint32_t sB32 = sbase + B32_OFF + (ktc % 3) * B32_BYTES;
        const uint32_t sB16 = sbase + B16_OFF + (ktc & 1) * B16_BYTES;
        const bool phase2 = (ktc >= 64);
        const int k0 = (ktc & 63) * BK;
        // 1024 units of 8 fp32 -> 2 per thread
        #pragma unroll
        for (int j = 0; j < 2; j++) {
            int id = tid + NTHR * j;
            int row = id >> 4, c8 = id & 15;
            float4 f0, f1;
            uint32_t src = sB32 + row * 512 + c8 * 32;
            asm volatile("ld.shared.v4.f32 {%0,%1,%2,%3}, [%4];"
                         : "=f"(f0.x), "=f"(f0.y), "=f"(f0.z), "=f"(f0.w) : "r"(src));
            asm volatile("ld.shared.v4.f32 {%0,%1,%2,%3}, [%4];"
                         : "=f"(f1.x), "=f"(f1.y), "=f"(f1.z), "=f"(f1.w) : "r"(src + 16));
            if (phase2) {
                float b = __ldg(bias + k0 + row);
                f0.x = fmaxf(f0.x + b, 0.0f); f0.y = fmaxf(f0.y + b, 0.0f);
                f0.z = fmaxf(f0.z + b, 0.0f); f0.w = fmaxf(f0.w + b, 0.0f);
                f1.x = fmaxf(f1.x + b, 0.0f); f1.y = fmaxf(f1.y + b, 0.0f);
                f1.z = fmaxf(f1.z + b, 0.0f); f1.w = fmaxf(f1.w + b, 0.0f);
            }
            __half2 h0 = __float22half2_rn({f0.x, f0.y});
            __half2 h1 = __float22half2_rn({f0.z, f0.w});
            __half2 h2 = __float22half2_rn({f1.x, f1.y});
            __half2 h3 = __float22half2_rn({f1.z, f1.w});
            uint32_t dst = sB16 + row * (LDB * 2) + c8 * 16;
            asm volatile("st.shared.v4.b32 [%0], {%1,%2,%3,%4};"
                         :: "r"(dst),
                            "r"(*(uint32_t*)&h0), "r"(*(uint32_t*)&h1),
                            "r"(*(uint32_t*)&h2), "r"(*(uint32_t*)&h3));
        }
    };

    // ---- prologue: loads {0,1,2} in flight, convert stage 0 ----------------
    load_stage(0); CP_COMMIT();
    load_stage(1); CP_COMMIT();
    load_stage(2); CP_COMMIT();
    CP_WAIT2();                 // my stage-0 copies retired
    __syncthreads();            // all threads' stage-0 data visible
    convert_stage(0);

    const uint32_t aoff = (warp_m * 32 + (lane & 15)) * (LDA * 2) + (lane >> 4) * 16;
    const uint32_t boff = (lane & 15) * (LDB * 2) + warp_n * 64;

    for (int kt = 0; kt < nK; kt++) {
        // outstanding (this thread): {kt+1, kt+2}
        CP_WAIT1();             // stage kt+1 retired (for convert below)
        __syncthreads();        // publish everyone's kt+1 data + convert(kt);
                                // all compute(kt-1) reads done
        if (kt + 3 < nK) { load_stage(kt + 3); CP_COMMIT(); }
        if (kt + 1 < nK) convert_stage(kt + 1);

        const uint32_t sA   = sbase + A_OFF + (kt & 3) * A_BYTES;
        const uint32_t sB16 = sbase + B16_OFF + (kt & 1) * B16_BYTES;

        #pragma unroll
        for (int ks = 0; ks < 4; ks++) {
            uint32_t ah[2][4], bh[4][2];
            #pragma unroll
            for (int mi = 0; mi < 2; mi++) {
                uint32_t a = aoff + mi * 16 * (LDA * 2) + ks * 32;
                ldmx4(ah[mi], sA + a);
            }
            #pragma unroll
            for (int ni = 0; ni < 4; ni++) {
                uint32_t b = boff + ks * 16 * (LDB * 2) + ni * 16;
                ldmx2t(bh[ni], sB16 + b);
            }
            #pragma unroll
            for (int mi = 0; mi < 2; mi++)
                #pragma unroll
                for (int ni = 0; ni < 4; ni++)
                    mma_f16(acc[mi][ni], ah[mi], bh[ni]);
        }
    }

    // ---- epilogue: add D[m], write float2 per fragment pair ----------------
    #pragma unroll
    for (int mi = 0; mi < 2; mi++) {
        const int r0 = bm + warp_m * 32 + mi * 16 + (lane >> 2);
        const int r1 = r0 + 8;
        const float d0 = g_D[r0];
        const float d1 = g_D[r1];
        #pragma unroll
        for (int ni = 0; ni < 4; ni++) {
            const int c = bn + warp_n * 32 + ni * 8 + (lane & 3) * 2;
            float2 v0 = {acc[mi][ni][0] + d0, acc[mi][ni][1] + d0};
            float2 v1 = {acc[mi][ni][2] + d1, acc[mi][ni][3] + d1};
            *(float2*)(out + (size_t)r0 * I_DIM + c) = v0;
            *(float2*)(out + (size_t)r1 * I_DIM + c) = v1;
        }
    }
}

// ===================== launch ==============================================
extern "C" void kernel_launch(void* const* d_in, const int* in_sizes, int n_in,
                              void* d_out, int out_size) {
    const float* last_uA = (const float*)d_in[0];  // [1, 512, 4096]
    const float* weight  = (const float*)d_in[1];  // [4096, 4096]
    const float* bias    = (const float*)d_in[2];  // [4096]
    const float* lbp     = (const float*)d_in[3];  // [1, 4096]
    const float* ubp     = (const float*)d_in[4];  // [1, 4096]
    const float* alpha   = (const float*)d_in[5];  // [1, 4096, 1]
    float* out = (float*)d_out;                    // uA then ubias

    cudaFuncSetAttribute(kern_gemm_mma,
                         cudaFuncAttributeMaxDynamicSharedMemorySize, SMEM_DYN);

    kern_prep<<<O_DIM / 256, 256>>>(bias, lbp, ubp, alpha);
    kern_coeff<<<S_DIM, 256>>>(last_uA, out + (size_t)S_DIM * I_DIM);
    kern_gemm_mma<<<dim3(I_DIM / BN, S_DIM / BM), NTHR, SMEM_DYN>>>(weight, bias, out);
}

// round 15
// speedup vs baseline: 1.0963x; 1.0963x over previous
#include <cuda_runtime.h>
#include <cuda_fp16.h>
#include <cstdint>

#define S_DIM 512
#define O_DIM 4096
#define I_DIM 4096

// ===================== device-global scratch ===============================
__device__ float g_D[S_DIM];
__device__ int   g_anyC2 = 0;   // zero-init; atomicOr idempotent across replays

// fp16 operand matrices
__device__ __align__(16) __half g_A1 [S_DIM * O_DIM];
__device__ __align__(16) __half g_A2 [S_DIM * O_DIM];
__device__ __align__(16) __half g_Wh [(size_t)O_DIM * I_DIM];
__device__ __align__(16) __half g_Rh [(size_t)O_DIM * I_DIM];   // stays 0 for stable rows

__device__ __forceinline__ uint32_t smem_u32(const void* p) {
    uint32_t a;
    asm("{ .reg .u64 t; cvta.to.shared.u64 t, %1; cvt.u32.u64 %0, t; }"
        : "=r"(a) : "l"(p));
    return a;
}
#define CP_ASYNC16(s, g) \
    asm volatile("cp.async.cg.shared.global [%0], [%1], 16;" :: "r"(s), "l"(g))
#define CP_COMMIT() asm volatile("cp.async.commit_group;" ::: "memory")
#define CP_WAIT2()  asm volatile("cp.async.wait_group 2;" ::: "memory")

__device__ __forceinline__ void ldmx4(uint32_t* r, uint32_t addr) {
    asm volatile("ldmatrix.sync.aligned.m8n8.x4.shared.b16 {%0,%1,%2,%3}, [%4];"
                 : "=r"(r[0]), "=r"(r[1]), "=r"(r[2]), "=r"(r[3]) : "r"(addr));
}
__device__ __forceinline__ void ldmx2t(uint32_t* r, uint32_t addr) {
    asm volatile("ldmatrix.sync.aligned.m8n8.x2.trans.shared.b16 {%0,%1}, [%2];"
                 : "=r"(r[0]), "=r"(r[1]) : "r"(addr));
}
__device__ __forceinline__ void mma_f16(float* c, const uint32_t* a, const uint32_t* b) {
    asm volatile("mma.sync.aligned.m16n8k16.row.col.f32.f16.f16.f32 "
                 "{%0,%1,%2,%3}, {%4,%5,%6,%7}, {%8,%9}, {%0,%1,%2,%3};"
                 : "+f"(c[0]), "+f"(c[1]), "+f"(c[2]), "+f"(c[3])
                 : "r"(a[0]), "r"(a[1]), "r"(a[2]), "r"(a[3]), "r"(b[0]), "r"(b[1]));
}

// ---- shared per-neuron scalar derivation (matches reference semantics) ----
struct NeuronScalars { float P1, N1, P2, PB, NB; };
__device__ __forceinline__ NeuronScalars derive_scalars(float b, float lb,
                                                        float ub, float a) {
    float one_a = 1.0f - a;
    float lb_r = fminf(lb, 0.0f);
    float ub_r = fmaxf(ub, 0.0f);
    ub_r = fmaxf(ub_r, lb_r + 1e-8f);
    float ud  = ub_r / (ub_r - lb_r);
    float upb = -lb_r * ud;
    float ldv = (ud > 0.5f) ? 1.0f : 0.0f;
    float lower_d = (fabsf(lb) >= fabsf(ub)) ? 1.0f : 0.0f;

    NeuronScalars s;
    if (ub <= 0.0f) {
        s.P1 = a * ud;           s.N1 = a * ldv;                    s.P2 = 0.0f;
        s.PB = upb + ud * a * b; s.NB = ldv * a * b;
    } else if (lb >= 0.0f) {
        s.P1 = a * ud + one_a;   s.N1 = a * ldv + one_a;            s.P2 = 0.0f;
        s.PB = one_a * b + upb + ud * a * b;
        s.NB = one_a * b + ldv * a * b;
    } else {
        s.P1 = a * ud;           s.N1 = a * ldv + one_a * lower_d;  s.P2 = one_a;
        s.PB = one_a * fmaxf(b, 0.0f) + upb + ud * a * b;
        s.NB = one_a * lower_d * b + ldv * a * b;
    }
    return s;
}

// ===================== kernel 1: W -> fp16 (self-deciding relu path) =======
__global__ void kern_wsplit(const float* __restrict__ W,
                            const float* __restrict__ bias,
                            const float* __restrict__ lbp,
                            const float* __restrict__ ubp,
                            const float* __restrict__ alpha) {
    size_t base = ((size_t)blockIdx.x * blockDim.x + threadIdx.x) * 4;
    int o = (int)(base >> 12);   // base / 4096
    float4 w4 = *(const float4*)(W + base);
    float wv[4] = {w4.x, w4.y, w4.z, w4.w};
    __half2 h01 = {__float2half_rn(wv[0]), __float2half_rn(wv[1])};
    __half2 h23 = {__float2half_rn(wv[2]), __float2half_rn(wv[3])};
    *(__half2*)(g_Wh + base)     = h01;
    *(__half2*)(g_Wh + base + 2) = h23;

    // relu(W+b) row only needed when this neuron is unstable AND alpha != 1.
    float lb = __ldg(lbp + o), ub = __ldg(ubp + o), a = __ldg(alpha + o);
    if (lb < 0.0f && ub > 0.0f && a != 1.0f) {
        float b = __ldg(bias + o);
        __half2 r01 = {__float2half_rn(fmaxf(wv[0] + b, 0.0f)),
                       __float2half_rn(fmaxf(wv[1] + b, 0.0f))};
        __half2 r23 = {__float2half_rn(fmaxf(wv[2] + b, 0.0f)),
                       __float2half_rn(fmaxf(wv[3] + b, 0.0f))};
        *(__half2*)(g_Rh + base)     = r01;
        *(__half2*)(g_Rh + base + 2) = r23;
    }
}

// ===================== kernel 2: coefficients (inline prep) ================
__global__ void kern_coeff(const float* __restrict__ last_uA,
                           const float* __restrict__ bias,
                           const float* __restrict__ lbp,
                           const float* __restrict__ ubp,
                           const float* __restrict__ alpha,
                           float* __restrict__ ubias_out) {
    int s = blockIdx.x;
    const float* row = last_uA + (size_t)s * O_DIM;

    float accB = 0.0f, accD = 0.0f;
    bool anyc2 = false;
    for (int o = threadIdx.x; o < O_DIM; o += blockDim.x) {
        float u  = row[o];
        float b  = __ldg(bias + o);
        float lb = __ldg(lbp + o);
        float ub = __ldg(ubp + o);
        float a  = __ldg(alpha + o);
        NeuronScalars ns = derive_scalars(b, lb, ub, a);

        float p = fmaxf(u, 0.0f);
        float n = fminf(u, 0.0f);
        float c1 = p * ns.P1 + n * ns.N1;
        float c2 = p * ns.P2;
        size_t idx = (size_t)s * O_DIM + o;
        g_A1[idx] = __float2half_rn(c1);
        g_A2[idx] = __float2half_rn(c2);
        accB = fmaf(p, ns.PB, accB);
        accB = fmaf(n, ns.NB, accB);
        accD = fmaf(c2, -fmaxf(b, 0.0f), accD);
        anyc2 |= (ns.P2 != 0.0f);
    }
    // flag: one atomic per warp at most
    if (__ballot_sync(0xffffffffu, anyc2) && (threadIdx.x & 31) == 0)
        atomicOr(&g_anyC2, 1);

    __shared__ float sB[8], sD[8];
    #pragma unroll
    for (int off = 16; off > 0; off >>= 1) {
        accB += __shfl_down_sync(0xffffffffu, accB, off);
        accD += __shfl_down_sync(0xffffffffu, accD, off);
    }
    int wid = threadIdx.x >> 5, lid = threadIdx.x & 31;
    if (lid == 0) { sB[wid] = accB; sD[wid] = accD; }
    __syncthreads();
    if (threadIdx.x == 0) {
        float tB = 0.0f, tD = 0.0f;
        #pragma unroll
        for (int w = 0; w < 8; w++) { tB += sB[w]; tD += sD[w]; }
        ubias_out[s] = tB;
        g_D[s] = tD;
    }
}

// ===================== kernel 3: mma.sync fp16 GEMM (R13 config) ===========
// out[m,i] = sum_o fp16(C1)[m,o]*fp16(W)[o,i] (+ C2 path) + D[m]
// BM=128 x BN=128, 512 threads (4 warps/SMSP), grid 128, 4-stage pipeline.
#define BM 128
#define BN 128
#define BK 64
#define NTHR 512
#define LDA 72            // (BK+8) fp16 elems, 144 bytes/row
#define LDB 136           // (BN+8) fp16 elems, 272 bytes/row
#define A_BYTES (BM * LDA * 2)        // 18432
#define B_BYTES (BK * LDB * 2)        // 17408
#define STAGE   (A_BYTES + B_BYTES)   // 35840
#define NSTAGE  4
#define SMEM_DYN (NSTAGE * STAGE)     // 143360

__global__ void __launch_bounds__(NTHR, 1)
kern_gemm_mma(float* __restrict__ out) {
    extern __shared__ char sm[];
    const uint32_t sbase = smem_u32(sm);

    const int tid  = threadIdx.x;
    const int wid  = tid >> 5;
    const int lane = tid & 31;
    const int bn = blockIdx.x * BN;
    const int bm = blockIdx.y * BM;
    const bool useC2 = (g_anyC2 != 0);
    const int nK = useC2 ? 128 : 64;

    const int warp_m = wid & 3;      // 0..3 -> 32 rows each
    const int warp_n = wid >> 2;     // 0..3 -> 32 cols each

    float acc[2][4][4];
    #pragma unroll
    for (int mi = 0; mi < 2; mi++)
        #pragma unroll
        for (int ni = 0; ni < 4; ni++)
            #pragma unroll
            for (int q = 0; q < 4; q++) acc[mi][ni][q] = 0.0f;

    auto load_stage = [&](int ktL) {
        const int buf = ktL & (NSTAGE - 1);
        const int k0 = (ktL & 63) * BK;
        const __half *pA, *pB;
        if (ktL < 64) { pA = g_A1; pB = g_Wh; }
        else          { pA = g_A2; pB = g_Rh; }
        const uint32_t sA = sbase + buf * STAGE;
        const uint32_t sB = sA + A_BYTES;

        #pragma unroll
        for (int j = 0; j < 2; j++) {           // A: 128 rows x 8 chunks
            int id = tid + NTHR * j;
            int ar = id >> 3, ac = id & 7;
            size_t gA = (size_t)(bm + ar) * O_DIM + k0 + ac * 8;
            CP_ASYNC16(sA + ar * (LDA * 2) + ac * 16, pA + gA);
        }
        #pragma unroll
        for (int j = 0; j < 2; j++) {           // B: 64 rows x 16 chunks
            int id = tid + NTHR * j;
            int br = id >> 4, bc = id & 15;
            size_t gB = (size_t)(k0 + br) * I_DIM + bn + bc * 8;
            CP_ASYNC16(sB + br * (LDB * 2) + bc * 16, pB + gB);
        }
    };

    // prologue: fill 3 of 4 stages
    load_stage(0); CP_COMMIT();
    load_stage(1); CP_COMMIT();
    load_stage(2); CP_COMMIT();

    const uint32_t aoff = (warp_m * 32 + (lane & 15)) * (LDA * 2) + (lane >> 4) * 16;
    const uint32_t boff = (lane & 15) * (LDB * 2) + warp_n * 64;

    for (int kt = 0; kt < nK; kt++) {
        // Outstanding groups (this thread): loads kt, kt+1, kt+2.
        CP_WAIT2();             // my stage-kt copies retired
        __syncthreads();        // everyone's stage-kt data visible;
                                // all threads done with compute(kt-1)
        if (kt + 3 < nK) load_stage(kt + 3);   // overwrites buf (kt-1)%4: safe
        CP_COMMIT();

        const int buf = kt & (NSTAGE - 1);
        const uint32_t sA = sbase + buf * STAGE;
        const uint32_t sB = sA + A_BYTES;

        #pragma unroll
        for (int ks = 0; ks < 4; ks++) {
            uint32_t ah[2][4], bh[4][2];
            #pragma unroll
            for (int mi = 0; mi < 2; mi++) {
                uint32_t a = aoff + mi * 16 * (LDA * 2) + ks * 32;
                ldmx4(ah[mi], sA + a);
            }
            #pragma unroll
            for (int ni = 0; ni < 4; ni++) {
                uint32_t b = boff + ks * 16 * (LDB * 2) + ni * 16;
                ldmx2t(bh[ni], sB + b);
            }
            #pragma unroll
            for (int mi = 0; mi < 2; mi++)
                #pragma unroll
                for (int ni = 0; ni < 4; ni++)
                    mma_f16(acc[mi][ni], ah[mi], bh[ni]);
        }
    }

    // ---- epilogue: add D[m], write float2 per fragment pair
    #pragma unroll
    for (int mi = 0; mi < 2; mi++) {
        const int r0 = bm + warp_m * 32 + mi * 16 + (lane >> 2);
        const int r1 = r0 + 8;
        const float d0 = g_D[r0];
        const float d1 = g_D[r1];
        #pragma unroll
        for (int ni = 0; ni < 4; ni++) {
            const int c = bn + warp_n * 32 + ni * 8 + (lane & 3) * 2;
            float2 v0 = {acc[mi][ni][0] + d0, acc[mi][ni][1] + d0};
            float2 v1 = {acc[mi][ni][2] + d1, acc[mi][ni][3] + d1};
            *(float2*)(out + (size_t)r0 * I_DIM + c) = v0;
            *(float2*)(out + (size_t)r1 * I_DIM + c) = v1;
        }
    }
}

// ===================== launch ==============================================
extern "C" void kernel_launch(void* const* d_in, const int* in_sizes, int n_in,
                              void* d_out, int out_size) {
    const float* last_uA = (const float*)d_in[0];  // [1, 512, 4096]
    const float* weight  = (const float*)d_in[1];  // [4096, 4096]
    const float* bias    = (const float*)d_in[2];  // [4096]
    const float* lbp     = (const float*)d_in[3];  // [1, 4096]
    const float* ubp     = (const float*)d_in[4];  // [1, 4096]
    const float* alpha   = (const float*)d_in[5];  // [1, 4096, 1]
    float* out = (float*)d_out;                    // uA then ubias

    cudaFuncSetAttribute(kern_gemm_mma,
                         cudaFuncAttributeMaxDynamicSharedMemorySize, SMEM_DYN);

    kern_wsplit<<<(int)(((size_t)O_DIM * I_DIM / 4) / 256), 256>>>(
        weight, bias, lbp, ubp, alpha);
    kern_coeff<<<S_DIM, 256>>>(last_uA, bias, lbp, ubp, alpha,
                               out + (size_t)S_DIM * I_DIM);
    kern_gemm_mma<<<dim3(I_DIM / BN, S_DIM / BM), NTHR, SMEM_DYN>>>(out);
}